// round 11
// baseline (speedup 1.0000x reference)
#include <cuda_runtime.h>
#include <cuda_bf16.h>
#include <cstdint>

// Problem constants
#define BATCH 2
#define SEQ   2048
#define DMODEL 4096
#define NHEADS 32
#define NKVH   8
#define HEADD  128
#define REP    4            // NHEADS / NKVH
#define NROWS  (BATCH*SEQ)  // 4096

typedef unsigned long long ull;

// ---------------- scratch (device globals: no runtime allocation) ----------------
__device__ float g_q[(size_t)NROWS * DMODEL];          // (B*L, H*HD)   64 MB
__device__ float g_k[(size_t)NROWS * NKVH * HEADD];    // (B*L, KVH*HD) 16 MB
__device__ float g_v[(size_t)NROWS * NKVH * HEADD];    // 16 MB
__device__ float g_attn[(size_t)NROWS * DMODEL];       // 64 MB

// ---------------- f32x2 packed helpers (flash kernel) ----------------
__device__ __forceinline__ ull pk2(float lo, float hi) {
    ull r; asm("mov.b64 %0, {%1,%2};" : "=l"(r) : "f"(lo), "f"(hi)); return r;
}
__device__ __forceinline__ void up2(ull v, float &lo, float &hi) {
    asm("mov.b64 {%0,%1}, %2;" : "=f"(lo), "=f"(hi) : "l"(v));
}
__device__ __forceinline__ ull f2fma(ull a, ull b, ull c) {
    ull d; asm("fma.rn.f32x2 %0, %1, %2, %3;" : "=l"(d) : "l"(a), "l"(b), "l"(c)); return d;
}
__device__ __forceinline__ ull f2mul(ull a, ull b) {
    ull d; asm("mul.rn.f32x2 %0, %1, %2;" : "=l"(d) : "l"(a), "l"(b)); return d;
}

// ---------------- tf32 split helper ----------------
// a = hi + lo with both tf32-representable; hi*b_hi + hi*b_lo + lo*b_hi
// recovers ~fp32 accuracy (3xTF32 scheme).
__device__ __forceinline__ float2 split_tf32(float a) {
    unsigned hb; asm("cvt.rna.tf32.f32 %0, %1;" : "=r"(hb) : "f"(a));
    float hi = __uint_as_float(hb);
    float lo = a - hi;
    unsigned lb; asm("cvt.rna.tf32.f32 %0, %1;" : "=r"(lb) : "f"(lo));
    return make_float2(hi, __uint_as_float(lb));
}

#define MMA_TF32(d0,d1,d2,d3,a0,a1,a2,a3,b0,b1)                               \
    asm volatile("mma.sync.aligned.m16n8k8.row.col.f32.tf32.tf32.f32 "        \
                 "{%0,%1,%2,%3}, {%4,%5,%6,%7}, {%8,%9}, {%0,%1,%2,%3};"      \
                 : "+f"(d0), "+f"(d1), "+f"(d2), "+f"(d3)                     \
                 : "r"(a0), "r"(a1), "r"(a2), "r"(a3), "r"(b0), "r"(b1))

// =================================================================================
// Tensor-core SGEMM (3xTF32): C[M,N] = A[M,K] @ B[K,N], row-major fp32.
// CTA tile 128x128, BK=16, 128 threads = 4 warps, warp tile 64x64.
// Smem holds (hi,lo) tf32 pairs; padded strides make fragment LDS.64
// conflict-free. 96 mma + 32 LDS.64 per warp per k-slice(8).
// Requires M%128==0, N%128==0, K%16==0.
// =================================================================================
#define GA_STRIDE 20    // pairs per A row (16 + pad)
#define GB_STRIDE 132   // pairs per B row (128 + pad)

__global__ void __launch_bounds__(128) sgemm_tf32x3(
    const float* __restrict__ A, const float* __restrict__ B,
    float* __restrict__ C, int M, int N, int K)
{
    __shared__ __align__(16) float2 As[128 * GA_STRIDE];  // [m][k] pairs
    __shared__ __align__(16) float2 Bs[16 * GB_STRIDE];   // [k][n] pairs

    const int t    = threadIdx.x;
    const int lane = t & 31;
    const int warp = t >> 5;
    const int wm   = (warp & 1) << 6;   // 0 or 64
    const int wn   = (warp >> 1) << 6;  // 0 or 64
    const int m0   = blockIdx.y << 7, n0 = blockIdx.x << 7;

    // staging maps
    const float* Ap = A + (size_t)(m0 + t) * K;                       // row t, 16 k/stage
    const int brow = t >> 3, bcol = (t & 7) << 4;                     // B: row k, 16 n/thread
    const float* Bp = B + (size_t)brow * N + n0 + bcol;

    float4 av[4], bv[4];
#pragma unroll
    for (int j = 0; j < 4; ++j) {
        av[j] = *(const float4*)(Ap + 4 * j);
        bv[j] = *(const float4*)(Bp + 4 * j);
    }

    float acc[4][8][4];
#pragma unroll
    for (int i = 0; i < 4; ++i)
#pragma unroll
        for (int j = 0; j < 8; ++j)
#pragma unroll
            for (int e = 0; e < 4; ++e) acc[i][j][e] = 0.0f;

    const int lq = lane >> 2;   // lane/4
    const int lr = lane & 3;    // lane%4

    for (int k0 = 0; k0 < K; k0 += 16) {
        // ---- stage (with tf32 hi/lo split) ----
#pragma unroll
        for (int j = 0; j < 4; ++j) {
            const float a4[4] = {av[j].x, av[j].y, av[j].z, av[j].w};
            const float b4[4] = {bv[j].x, bv[j].y, bv[j].z, bv[j].w};
#pragma unroll
            for (int e = 0; e < 4; ++e) {
                As[t * GA_STRIDE + 4 * j + e]             = split_tf32(a4[e]);
                Bs[brow * GB_STRIDE + bcol + 4 * j + e]   = split_tf32(b4[e]);
            }
        }
        __syncthreads();

        // ---- prefetch next stage ----
        if (k0 + 16 < K) {
#pragma unroll
            for (int j = 0; j < 4; ++j) {
                av[j] = *(const float4*)(Ap + k0 + 16 + 4 * j);
                bv[j] = *(const float4*)(Bp + (size_t)(k0 + 16) * N + 4 * j);
            }
        }

        // ---- compute: 2 k-slices of 8 ----
#pragma unroll
        for (int ks = 0; ks < 2; ++ks) {
            const int kb = (ks << 3) + lr;
            // B fragments for all 8 N atoms (hi & lo)
            unsigned bhi[8][2], blo[8][2];
#pragma unroll
            for (int na = 0; na < 8; ++na) {
                const int n = wn + (na << 3) + lq;
                float2 p0 = Bs[kb * GB_STRIDE + n];
                float2 p1 = Bs[(kb + 4) * GB_STRIDE + n];
                bhi[na][0] = __float_as_uint(p0.x); blo[na][0] = __float_as_uint(p0.y);
                bhi[na][1] = __float_as_uint(p1.x); blo[na][1] = __float_as_uint(p1.y);
            }
#pragma unroll
            for (int ma = 0; ma < 4; ++ma) {
                const int r = wm + (ma << 4) + lq;
                float2 q0 = As[r * GA_STRIDE + kb];
                float2 q1 = As[(r + 8) * GA_STRIDE + kb];
                float2 q2 = As[r * GA_STRIDE + kb + 4];
                float2 q3 = As[(r + 8) * GA_STRIDE + kb + 4];
                unsigned ah0 = __float_as_uint(q0.x), al0 = __float_as_uint(q0.y);
                unsigned ah1 = __float_as_uint(q1.x), al1 = __float_as_uint(q1.y);
                unsigned ah2 = __float_as_uint(q2.x), al2 = __float_as_uint(q2.y);
                unsigned ah3 = __float_as_uint(q3.x), al3 = __float_as_uint(q3.y);
#pragma unroll
                for (int na = 0; na < 8; ++na) {
                    float* d = acc[ma][na];
                    MMA_TF32(d[0], d[1], d[2], d[3], ah0, ah1, ah2, ah3, bhi[na][0], bhi[na][1]);
                    MMA_TF32(d[0], d[1], d[2], d[3], ah0, ah1, ah2, ah3, blo[na][0], blo[na][1]);
                    MMA_TF32(d[0], d[1], d[2], d[3], al0, al1, al2, al3, bhi[na][0], bhi[na][1]);
                }
            }
        }
        __syncthreads();
    }

    // ---- epilogue ----
#pragma unroll
    for (int ma = 0; ma < 4; ++ma) {
#pragma unroll
        for (int na = 0; na < 8; ++na) {
            const int row = m0 + wm + (ma << 4) + lq;
            const int col = n0 + wn + (na << 3) + ((lane & 3) << 1);
            float* c0 = C + (size_t)row * N + col;
            float* c1 = C + (size_t)(row + 8) * N + col;
            *(float2*)c0 = make_float2(acc[ma][na][0], acc[ma][na][1]);
            *(float2*)c1 = make_float2(acc[ma][na][2], acc[ma][na][3]);
        }
    }
}

// =================================================================================
// RoPE (interleaved pairs within each head), in-place on (B*L, NH*128) buffer.
// =================================================================================
template <int NH>
__global__ void rope_kernel(float* __restrict__ buf,
                            const float* __restrict__ ct,
                            const float* __restrict__ st, int total)
{
    int idx = blockIdx.x * blockDim.x + threadIdx.x;   // pair index
    if (idx >= total) return;
    int p   = idx & 63;
    int h   = (idx >> 6) & (NH - 1);
    int row = idx / (64 * NH);
    int l   = row & (SEQ - 1);
    float c = ct[(l << 6) + p];
    float s = st[(l << 6) + p];
    float2* ptr = (float2*)(buf + ((size_t)row * NH + h) * HEADD + (p << 1));
    float2 v = *ptr;
    *ptr = make_float2(v.x * c - v.y * s, v.x * s + v.y * c);
}

// =================================================================================
// Flash attention (causal, GQA). BM=BN=64, HD=128. (unchanged from R5 pass)
// =================================================================================
#define FA_BM 64
#define FA_BN 64
#define QK_STRIDE 68
#define PS_STRIDE 65
#define FA_SMEM_FLOATS (2 * 128 * QK_STRIDE + FA_BN * 128 + FA_BM * PS_STRIDE)
#define FA_SMEM_BYTES  (FA_SMEM_FLOATS * 4)

__global__ void __launch_bounds__(256) flash_kernel(
    const float* __restrict__ q, const float* __restrict__ k,
    const float* __restrict__ v, float* __restrict__ out)
{
    extern __shared__ __align__(16) float sm[];
    float* Qt = sm;                         // [d][r] stride 68
    float* Kt = Qt + 128 * QK_STRIDE;       // [d][j] stride 68
    float* Vs = Kt + 128 * QK_STRIDE;       // [j][d] stride 128
    float* Ps = Vs + FA_BN * 128;           // [r][j] stride 65

    const int qb = blockIdx.x, h = blockIdx.y, b = blockIdx.z;
    const int kvh = h >> 2;   // REP = 4
    const int t  = threadIdx.x;
    const int tx = t & 15, ty = t >> 4;
    const int ty4 = ty << 2, tx4 = tx << 2, tx8 = tx << 3;
    const float scale = 0.08838834764831845f;   // 1/sqrt(128)

    const float* qbase = q + ((size_t)(b * SEQ + qb * FA_BM)) * DMODEL + h * HEADD;
    for (int i = t; i < FA_BM * 128; i += 256) {
        int r = i >> 7, d = i & 127;
        Qt[d * QK_STRIDE + r] = qbase[(size_t)r * DMODEL + d] * scale;
    }

    float m_i[4], l_i[4];
    ull  o2[4][4];
#pragma unroll
    for (int i = 0; i < 4; ++i) {
        m_i[i] = -1e30f; l_i[i] = 0.0f;
#pragma unroll
        for (int j = 0; j < 4; ++j) o2[i][j] = 0ull;
    }

    for (int kb = 0; kb <= qb; ++kb) {
        __syncthreads();

        const float* kbase = k + ((size_t)(b * SEQ + kb * FA_BN)) * (NKVH * HEADD) + kvh * HEADD;
        const float* vbase = v + ((size_t)(b * SEQ + kb * FA_BN)) * (NKVH * HEADD) + kvh * HEADD;
        for (int i = t; i < FA_BN * 128; i += 256) {
            int r = i >> 7, d = i & 127;
            Kt[d * QK_STRIDE + r] = kbase[(size_t)r * (NKVH * HEADD) + d];
        }
        for (int i = t; i < FA_BN * 128 / 4; i += 256) {
            int r = i >> 5, c4 = (i & 31) << 2;
            *(float4*)&Vs[r * 128 + c4] = *(const float4*)&vbase[(size_t)r * (NKVH * HEADD) + c4];
        }
        __syncthreads();

        ull s2[4][2] = {{0ull,0ull},{0ull,0ull},{0ull,0ull},{0ull,0ull}};
#pragma unroll 8
        for (int d = 0; d < 128; ++d) {
            const float* kr = &Kt[d * QK_STRIDE];
            ull b01 = *(const ull*)(kr + tx4);
            ull b23 = *(const ull*)(kr + tx4 + 2);
            float4 a = *(const float4*)&Qt[d * QK_STRIDE + ty4];
            float avv[4] = {a.x, a.y, a.z, a.w};
#pragma unroll
            for (int i = 0; i < 4; ++i) {
                ull aa = pk2(avv[i], avv[i]);
                s2[i][0] = f2fma(aa, b01, s2[i][0]);
                s2[i][1] = f2fma(aa, b23, s2[i][1]);
            }
        }
        float s[4][4];
#pragma unroll
        for (int i = 0; i < 4; ++i) {
            up2(s2[i][0], s[i][0], s[i][1]);
            up2(s2[i][1], s[i][2], s[i][3]);
        }

        if (kb == qb) {
#pragma unroll
            for (int i = 0; i < 4; ++i)
#pragma unroll
                for (int j = 0; j < 4; ++j)
                    if (tx4 + j > ty4 + i) s[i][j] = -1e30f;
        }

        float p[4][4], rsum[4], alpha[4];
#pragma unroll
        for (int i = 0; i < 4; ++i) {
            float mx = fmaxf(fmaxf(s[i][0], s[i][1]), fmaxf(s[i][2], s[i][3]));
#pragma unroll
            for (int off = 8; off >= 1; off >>= 1)
                mx = fmaxf(mx, __shfl_xor_sync(0xffffffffu, mx, off));
            float mn = fmaxf(m_i[i], mx);
            alpha[i] = __expf(m_i[i] - mn);
            m_i[i] = mn;
            float rs = 0.0f;
#pragma unroll
            for (int j = 0; j < 4; ++j) {
                p[i][j] = __expf(s[i][j] - mn);
                rs += p[i][j];
            }
#pragma unroll
            for (int off = 8; off >= 1; off >>= 1)
                rs += __shfl_xor_sync(0xffffffffu, rs, off);
            rsum[i] = rs;
        }
#pragma unroll
        for (int i = 0; i < 4; ++i) {
            l_i[i] = l_i[i] * alpha[i] + rsum[i];
            ull al2 = pk2(alpha[i], alpha[i]);
#pragma unroll
            for (int j = 0; j < 4; ++j) o2[i][j] = f2mul(o2[i][j], al2);
#pragma unroll
            for (int j = 0; j < 4; ++j) Ps[(ty4 + i) * PS_STRIDE + tx4 + j] = p[i][j];
        }
        __syncthreads();

#pragma unroll 4
        for (int j = 0; j < FA_BN; ++j) {
            const float* vr = &Vs[j * 128 + tx8];
            ull v0 = *(const ull*)(vr + 0);
            ull v1 = *(const ull*)(vr + 2);
            ull v2 = *(const ull*)(vr + 4);
            ull v3 = *(const ull*)(vr + 6);
#pragma unroll
            for (int i = 0; i < 4; ++i) {
                float pv = Ps[(ty4 + i) * PS_STRIDE + j];
                ull p2 = pk2(pv, pv);
                o2[i][0] = f2fma(p2, v0, o2[i][0]);
                o2[i][1] = f2fma(p2, v1, o2[i][1]);
                o2[i][2] = f2fma(p2, v2, o2[i][2]);
                o2[i][3] = f2fma(p2, v3, o2[i][3]);
            }
        }
    }

#pragma unroll
    for (int i = 0; i < 4; ++i) {
        float inv = 1.0f / l_i[i];
        float o[8];
        up2(o2[i][0], o[0], o[1]); up2(o2[i][1], o[2], o[3]);
        up2(o2[i][2], o[4], o[5]); up2(o2[i][3], o[6], o[7]);
#pragma unroll
        for (int jj = 0; jj < 8; ++jj) o[jj] *= inv;
        size_t row = (size_t)(b * SEQ + qb * FA_BM + ty4 + i);
        float* op = out + row * DMODEL + h * HEADD + tx8;
        *(float4*)(op + 0) = make_float4(o[0], o[1], o[2], o[3]);
        *(float4*)(op + 4) = make_float4(o[4], o[5], o[6], o[7]);
    }
}

// =================================================================================
// Host launcher
// =================================================================================
extern "C" void kernel_launch(void* const* d_in, const int* in_sizes, int n_in,
                              void* d_out, int out_size)
{
    const float* x   = (const float*)d_in[0];
    const float* wq  = (const float*)d_in[1];
    const float* wk  = (const float*)d_in[2];
    const float* wv  = (const float*)d_in[3];
    const float* wo  = (const float*)d_in[4];
    const float* fcos = (const float*)d_in[5];
    const float* fsin = (const float*)d_in[6];
    // d_in[7] = mask (causal, handled analytically), d_in[8] = start_pos (0)
    float* outp = (float*)d_out;

    float *gq, *gk, *gv, *ga;
    cudaGetSymbolAddress((void**)&gq, g_q);
    cudaGetSymbolAddress((void**)&gk, g_k);
    cudaGetSymbolAddress((void**)&gv, g_v);
    cudaGetSymbolAddress((void**)&ga, g_attn);

    cudaFuncSetAttribute(flash_kernel,
                         cudaFuncAttributeMaxDynamicSharedMemorySize, FA_SMEM_BYTES);

    // QKV projections (tensor-core 3xTF32)
    sgemm_tf32x3<<<dim3(DMODEL / 128, NROWS / 128), 128>>>(x, wq, gq, NROWS, DMODEL, DMODEL);
    sgemm_tf32x3<<<dim3((NKVH * HEADD) / 128, NROWS / 128), 128>>>(x, wk, gk, NROWS, NKVH * HEADD, DMODEL);
    sgemm_tf32x3<<<dim3((NKVH * HEADD) / 128, NROWS / 128), 128>>>(x, wv, gv, NROWS, NKVH * HEADD, DMODEL);

    // RoPE on q and k
    {
        int totq = NROWS * NHEADS * 64;
        int totk = NROWS * NKVH * 64;
        rope_kernel<NHEADS><<<(totq + 255) / 256, 256>>>(gq, fcos, fsin, totq);
        rope_kernel<NKVH><<<(totk + 255) / 256, 256>>>(gk, fcos, fsin, totk);
    }

    // Causal flash attention
    flash_kernel<<<dim3(SEQ / FA_BM, NHEADS, BATCH), 256, FA_SMEM_BYTES>>>(gq, gk, gv, ga);

    // Output projection -> d_out
    sgemm_tf32x3<<<dim3(DMODEL / 128, NROWS / 128), 128>>>(ga, wo, outp, NROWS, DMODEL, DMODEL);
}

// round 13
// speedup vs baseline: 1.8247x; 1.8247x over previous
#include <cuda_runtime.h>
#include <cuda_bf16.h>
#include <cstdint>

// Problem constants
#define BATCH 2
#define SEQ   2048
#define DMODEL 4096
#define NHEADS 32
#define NKVH   8
#define HEADD  128
#define REP    4
#define NROWS  (BATCH*SEQ)   // 4096
#define KVD    (NKVH*HEADD)  // 1024

typedef unsigned long long ull;

// ---------------- scratch (device globals: no runtime allocation) ----------------
__device__ float g_q[(size_t)NROWS * DMODEL];
__device__ float g_k[(size_t)NROWS * KVD];
__device__ float g_v[(size_t)NROWS * KVD];
__device__ float g_attn[(size_t)NROWS * DMODEL];

// bf16 2-way-split operand buffers (hi + lo)
__device__ __nv_bfloat16 s_xh[(size_t)NROWS * DMODEL],  s_xl[(size_t)NROWS * DMODEL];
__device__ __nv_bfloat16 s_ah[(size_t)NROWS * DMODEL],  s_al[(size_t)NROWS * DMODEL];
__device__ __nv_bfloat16 s_wqh[(size_t)DMODEL * DMODEL], s_wql[(size_t)DMODEL * DMODEL];
__device__ __nv_bfloat16 s_wkh[(size_t)KVD * DMODEL],    s_wkl[(size_t)KVD * DMODEL];
__device__ __nv_bfloat16 s_wvh[(size_t)KVD * DMODEL],    s_wvl[(size_t)KVD * DMODEL];
__device__ __nv_bfloat16 s_woh[(size_t)DMODEL * DMODEL], s_wol[(size_t)DMODEL * DMODEL];

// ---------------- f32x2 packed helpers (flash kernel) ----------------
__device__ __forceinline__ ull pk2(float lo, float hi) {
    ull r; asm("mov.b64 %0, {%1,%2};" : "=l"(r) : "f"(lo), "f"(hi)); return r;
}
__device__ __forceinline__ void up2(ull v, float &lo, float &hi) {
    asm("mov.b64 {%0,%1}, %2;" : "=f"(lo), "=f"(hi) : "l"(v));
}
__device__ __forceinline__ ull f2fma(ull a, ull b, ull c) {
    ull d; asm("fma.rn.f32x2 %0, %1, %2, %3;" : "=l"(d) : "l"(a), "l"(b), "l"(c)); return d;
}
__device__ __forceinline__ ull f2mul(ull a, ull b) {
    ull d; asm("mul.rn.f32x2 %0, %1, %2;" : "=l"(d) : "l"(a), "l"(b)); return d;
}

// ---------------- mma helpers (legacy mma.sync path: works on base sm_103) ----------
__device__ __forceinline__ uint32_t cvta_smem(const void* p) {
    uint32_t a;
    asm("{ .reg .u64 t; cvta.to.shared.u64 t, %1; cvt.u32.u64 %0, t; }" : "=r"(a) : "l"(p));
    return a;
}
__device__ __forceinline__ void cp16(uint32_t dst, const void* src) {
    asm volatile("cp.async.cg.shared.global [%0], [%1], 16;" :: "r"(dst), "l"(src));
}
__device__ __forceinline__ void ldsm4(uint32_t addr, uint32_t* r) {
    asm volatile("ldmatrix.sync.aligned.m8n8.x4.shared.b16 {%0,%1,%2,%3}, [%4];"
                 : "=r"(r[0]), "=r"(r[1]), "=r"(r[2]), "=r"(r[3]) : "r"(addr));
}
#define MMA_BF16(d, a, b0, b1)                                                  \
    asm volatile("mma.sync.aligned.m16n8k16.row.col.f32.bf16.bf16.f32 "         \
                 "{%0,%1,%2,%3},{%4,%5,%6,%7},{%8,%9},{%0,%1,%2,%3};"           \
                 : "+f"((d)[0]), "+f"((d)[1]), "+f"((d)[2]), "+f"((d)[3])       \
                 : "r"((a)[0]), "r"((a)[1]), "r"((a)[2]), "r"((a)[3]),          \
                   "r"(b0), "r"(b1))

// =================================================================================
// Split conversion kernels (fp32 -> bf16 hi + bf16 lo)
// =================================================================================
__global__ void convert_split2(const float* __restrict__ a,
                               __nv_bfloat16* __restrict__ h,
                               __nv_bfloat16* __restrict__ l, int n)
{
    int i = blockIdx.x * blockDim.x + threadIdx.x;
    if (i >= n) return;
    float v = a[i];
    __nv_bfloat16 hh = __float2bfloat16(v);
    float r1 = v - __bfloat162float(hh);
    h[i] = hh; l[i] = __float2bfloat16(r1);
}

// w[K][N] fp32  ->  T{h,l}[N][K] bf16
__global__ void transpose_split2(const float* __restrict__ w,
                                 __nv_bfloat16* __restrict__ th,
                                 __nv_bfloat16* __restrict__ tl, int K, int N)
{
    __shared__ float tile[32][33];
    int n0 = blockIdx.x * 32, k0 = blockIdx.y * 32;
    int tx = threadIdx.x, ty = threadIdx.y;  // (32, 8)
#pragma unroll
    for (int i = 0; i < 32; i += 8)
        tile[ty + i][tx] = w[(size_t)(k0 + ty + i) * N + n0 + tx];
    __syncthreads();
#pragma unroll
    for (int i = 0; i < 32; i += 8) {
        float v = tile[tx][ty + i];
        size_t o = (size_t)(n0 + ty + i) * K + k0 + tx;
        __nv_bfloat16 hh = __float2bfloat16(v);
        float r1 = v - __bfloat162float(hh);
        th[o] = hh; tl[o] = __float2bfloat16(r1);
    }
}

// =================================================================================
// bf16 split-GEMM via mma.sync.m16n8k16 (3 products: h.h + h.l + l.h):
// C[M,N] = A[M,K] @ BT[N,K]^T, fp32 accumulate.
// CTA 128x128, BK=32, 128 threads (4 warps, 64x64 each), double-buffered cp.async,
// ldmatrix.x4 fragment loads, smem rows padded to 40 bf16 (80B, conflict-free).
// =================================================================================
#define ROW_B   80                       // bytes per smem tile row (32 bf16 + pad)
#define TILE_B  (128 * ROW_B)            // 10240 B
#define BUF_B   (4 * TILE_B)             // Ah Al Bh Bl = 40960 B
#define GEMM_SMEM (2 * BUF_B)            // 81920 B

__global__ void __launch_bounds__(128, 2) gemm_bf16x3(
    const __nv_bfloat16* __restrict__ Ah, const __nv_bfloat16* __restrict__ Al,
    const __nv_bfloat16* __restrict__ Bh, const __nv_bfloat16* __restrict__ Bl,
    float* __restrict__ C, int K, int N)
{
    extern __shared__ __align__(16) char smem[];
    const uint32_t sb = cvta_smem(smem);
    const int t = threadIdx.x, warp = t >> 5, lane = t & 31;
    const int wm = (warp & 1) << 6, wn = (warp >> 1) << 6;
    const int m0 = blockIdx.y << 7, n0 = blockIdx.x << 7;

    const int S = K >> 5;   // BK = 32

    auto load_stage = [&](int s) {
        const uint32_t base = sb + (uint32_t)(s & 1) * BUF_B;
        const int k0 = s << 5;
        const __nv_bfloat16* srcs[4] = {
            Ah + (size_t)(m0 + t) * K + k0,
            Al + (size_t)(m0 + t) * K + k0,
            Bh + (size_t)(n0 + t) * K + k0,
            Bl + (size_t)(n0 + t) * K + k0
        };
#pragma unroll
        for (int ti = 0; ti < 4; ++ti) {
            uint32_t rowb = base + ti * TILE_B + (uint32_t)t * ROW_B;
#pragma unroll
            for (int c = 0; c < 4; ++c)
                cp16(rowb + c * 16, (const char*)srcs[ti] + c * 16);
        }
        asm volatile("cp.async.commit_group;");
    };

    float acc[4][8][4];
#pragma unroll
    for (int i = 0; i < 4; ++i)
#pragma unroll
        for (int j = 0; j < 8; ++j)
#pragma unroll
            for (int e = 0; e < 4; ++e) acc[i][j][e] = 0.0f;

    // ldmatrix per-lane address components
    const int q  = lane >> 3, rr = lane & 7;
    // A tile: q0: (row+0..7, k+0), q1: (+8, k+0), q2: (+0, k+8), q3: (+8, k+8)
    const int arow_off = rr + ((q & 1) << 3);
    const int acol_off = (q >> 1) << 4;            // bytes
    // B tile: q0: natom-even b0, q1: even b1, q2: odd b0, q3: odd b1
    const int brow_off = ((q >> 1) << 3) + rr;
    const int bcol_off = (q & 1) << 4;             // bytes

    load_stage(0);

    for (int s = 0; s < S; ++s) {
        if (s + 1 < S) {
            load_stage(s + 1);
            asm volatile("cp.async.wait_group 1;" ::: "memory");
        } else {
            asm volatile("cp.async.wait_group 0;" ::: "memory");
        }
        __syncthreads();

        const uint32_t bufb = sb + (uint32_t)(s & 1) * BUF_B;
        const uint32_t ta_h = bufb, ta_l = bufb + TILE_B;
        const uint32_t tb_h = bufb + 2 * TILE_B, tb_l = bufb + 3 * TILE_B;

#pragma unroll
        for (int ksub = 0; ksub < 2; ++ksub) {
            const int kb = ksub << 5;   // byte offset within row
            uint32_t bh[4][4], bl[4][4];
#pragma unroll
            for (int np = 0; np < 4; ++np) {
                uint32_t off = (uint32_t)(wn + (np << 4) + brow_off) * ROW_B + kb + bcol_off;
                ldsm4(tb_h + off, bh[np]);
                ldsm4(tb_l + off, bl[np]);
            }
#pragma unroll
            for (int ma = 0; ma < 4; ++ma) {
                uint32_t ah[4], al[4];
                uint32_t off = (uint32_t)(wm + (ma << 4) + arow_off) * ROW_B + kb + acol_off;
                ldsm4(ta_h + off, ah);
                ldsm4(ta_l + off, al);
#pragma unroll
                for (int na = 0; na < 8; ++na) {
                    const uint32_t* ph = &bh[na >> 1][(na & 1) << 1];
                    const uint32_t* pl = &bl[na >> 1][(na & 1) << 1];
                    float* d = acc[ma][na];
                    MMA_BF16(d, ah, ph[0], ph[1]);
                    MMA_BF16(d, ah, pl[0], pl[1]);
                    MMA_BF16(d, al, ph[0], ph[1]);
                }
            }
        }
        __syncthreads();
    }

    // epilogue
    const int g = lane >> 2, tq = lane & 3;
#pragma unroll
    for (int ma = 0; ma < 4; ++ma) {
#pragma unroll
        for (int na = 0; na < 8; ++na) {
            const int row = m0 + wm + (ma << 4) + g;
            const int col = n0 + wn + (na << 3) + (tq << 1);
            float* d = acc[ma][na];
            *(float2*)(C + (size_t)row * N + col)       = make_float2(d[0], d[1]);
            *(float2*)(C + (size_t)(row + 8) * N + col) = make_float2(d[2], d[3]);
        }
    }
}

// =================================================================================
// RoPE (unchanged)
// =================================================================================
template <int NH>
__global__ void rope_kernel(float* __restrict__ buf,
                            const float* __restrict__ ct,
                            const float* __restrict__ st, int total)
{
    int idx = blockIdx.x * blockDim.x + threadIdx.x;
    if (idx >= total) return;
    int p   = idx & 63;
    int h   = (idx >> 6) & (NH - 1);
    int row = idx / (64 * NH);
    int l   = row & (SEQ - 1);
    float c = ct[(l << 6) + p];
    float s = st[(l << 6) + p];
    float2* ptr = (float2*)(buf + ((size_t)row * NH + h) * HEADD + (p << 1));
    float2 v = *ptr;
    *ptr = make_float2(v.x * c - v.y * s, v.x * s + v.y * c);
}

// =================================================================================
// Flash attention (unchanged from R5 pass)
// =================================================================================
#define FA_BM 64
#define FA_BN 64
#define QK_STRIDE 68
#define PS_STRIDE 65
#define FA_SMEM_FLOATS (2 * 128 * QK_STRIDE + FA_BN * 128 + FA_BM * PS_STRIDE)
#define FA_SMEM_BYTES  (FA_SMEM_FLOATS * 4)

__global__ void __launch_bounds__(256) flash_kernel(
    const float* __restrict__ q, const float* __restrict__ k,
    const float* __restrict__ v, float* __restrict__ out)
{
    extern __shared__ __align__(16) float sm[];
    float* Qt = sm;
    float* Kt = Qt + 128 * QK_STRIDE;
    float* Vs = Kt + 128 * QK_STRIDE;
    float* Ps = Vs + FA_BN * 128;

    const int qb = blockIdx.x, h = blockIdx.y, b = blockIdx.z;
    const int kvh = h >> 2;
    const int t  = threadIdx.x;
    const int tx = t & 15, ty = t >> 4;
    const int ty4 = ty << 2, tx4 = tx << 2, tx8 = tx << 3;
    const float scale = 0.08838834764831845f;

    const float* qbase = q + ((size_t)(b * SEQ + qb * FA_BM)) * DMODEL + h * HEADD;
    for (int i = t; i < FA_BM * 128; i += 256) {
        int r = i >> 7, d = i & 127;
        Qt[d * QK_STRIDE + r] = qbase[(size_t)r * DMODEL + d] * scale;
    }

    float m_i[4], l_i[4];
    ull  o2[4][4];
#pragma unroll
    for (int i = 0; i < 4; ++i) {
        m_i[i] = -1e30f; l_i[i] = 0.0f;
#pragma unroll
        for (int j = 0; j < 4; ++j) o2[i][j] = 0ull;
    }

    for (int kb = 0; kb <= qb; ++kb) {
        __syncthreads();
        const float* kbase = k + ((size_t)(b * SEQ + kb * FA_BN)) * KVD + kvh * HEADD;
        const float* vbase = v + ((size_t)(b * SEQ + kb * FA_BN)) * KVD + kvh * HEADD;
        for (int i = t; i < FA_BN * 128; i += 256) {
            int r = i >> 7, d = i & 127;
            Kt[d * QK_STRIDE + r] = kbase[(size_t)r * KVD + d];
        }
        for (int i = t; i < FA_BN * 128 / 4; i += 256) {
            int r = i >> 5, c4 = (i & 31) << 2;
            *(float4*)&Vs[r * 128 + c4] = *(const float4*)&vbase[(size_t)r * KVD + c4];
        }
        __syncthreads();

        ull s2[4][2] = {{0ull,0ull},{0ull,0ull},{0ull,0ull},{0ull,0ull}};
#pragma unroll 8
        for (int d = 0; d < 128; ++d) {
            const float* kr = &Kt[d * QK_STRIDE];
            ull b01 = *(const ull*)(kr + tx4);
            ull b23 = *(const ull*)(kr + tx4 + 2);
            float4 a = *(const float4*)&Qt[d * QK_STRIDE + ty4];
            float avv[4] = {a.x, a.y, a.z, a.w};
#pragma unroll
            for (int i = 0; i < 4; ++i) {
                ull aa = pk2(avv[i], avv[i]);
                s2[i][0] = f2fma(aa, b01, s2[i][0]);
                s2[i][1] = f2fma(aa, b23, s2[i][1]);
            }
        }
        float s[4][4];
#pragma unroll
        for (int i = 0; i < 4; ++i) {
            up2(s2[i][0], s[i][0], s[i][1]);
            up2(s2[i][1], s[i][2], s[i][3]);
        }

        if (kb == qb) {
#pragma unroll
            for (int i = 0; i < 4; ++i)
#pragma unroll
                for (int j = 0; j < 4; ++j)
                    if (tx4 + j > ty4 + i) s[i][j] = -1e30f;
        }

        float p[4][4], rsum[4], alpha[4];
#pragma unroll
        for (int i = 0; i < 4; ++i) {
            float mx = fmaxf(fmaxf(s[i][0], s[i][1]), fmaxf(s[i][2], s[i][3]));
#pragma unroll
            for (int off = 8; off >= 1; off >>= 1)
                mx = fmaxf(mx, __shfl_xor_sync(0xffffffffu, mx, off));
            float mn = fmaxf(m_i[i], mx);
            alpha[i] = __expf(m_i[i] - mn);
            m_i[i] = mn;
            float rs = 0.0f;
#pragma unroll
            for (int j = 0; j < 4; ++j) {
                p[i][j] = __expf(s[i][j] - mn);
                rs += p[i][j];
            }
#pragma unroll
            for (int off = 8; off >= 1; off >>= 1)
                rs += __shfl_xor_sync(0xffffffffu, rs, off);
            rsum[i] = rs;
        }
#pragma unroll
        for (int i = 0; i < 4; ++i) {
            l_i[i] = l_i[i] * alpha[i] + rsum[i];
            ull al2 = pk2(alpha[i], alpha[i]);
#pragma unroll
            for (int j = 0; j < 4; ++j) o2[i][j] = f2mul(o2[i][j], al2);
#pragma unroll
            for (int j = 0; j < 4; ++j) Ps[(ty4 + i) * PS_STRIDE + tx4 + j] = p[i][j];
        }
        __syncthreads();

#pragma unroll 4
        for (int j = 0; j < FA_BN; ++j) {
            const float* vr = &Vs[j * 128 + tx8];
            ull v0 = *(const ull*)(vr + 0);
            ull v1 = *(const ull*)(vr + 2);
            ull v2 = *(const ull*)(vr + 4);
            ull v3 = *(const ull*)(vr + 6);
#pragma unroll
            for (int i = 0; i < 4; ++i) {
                float pv = Ps[(ty4 + i) * PS_STRIDE + j];
                ull p2 = pk2(pv, pv);
                o2[i][0] = f2fma(p2, v0, o2[i][0]);
                o2[i][1] = f2fma(p2, v1, o2[i][1]);
                o2[i][2] = f2fma(p2, v2, o2[i][2]);
                o2[i][3] = f2fma(p2, v3, o2[i][3]);
            }
        }
    }

#pragma unroll
    for (int i = 0; i < 4; ++i) {
        float inv = 1.0f / l_i[i];
        float o[8];
        up2(o2[i][0], o[0], o[1]); up2(o2[i][1], o[2], o[3]);
        up2(o2[i][2], o[4], o[5]); up2(o2[i][3], o[6], o[7]);
#pragma unroll
        for (int jj = 0; jj < 8; ++jj) o[jj] *= inv;
        size_t row = (size_t)(b * SEQ + qb * FA_BM + ty4 + i);
        float* op = out + row * DMODEL + h * HEADD + tx8;
        *(float4*)(op + 0) = make_float4(o[0], o[1], o[2], o[3]);
        *(float4*)(op + 4) = make_float4(o[4], o[5], o[6], o[7]);
    }
}

// =================================================================================
// Host launcher
// =================================================================================
extern "C" void kernel_launch(void* const* d_in, const int* in_sizes, int n_in,
                              void* d_out, int out_size)
{
    const float* x    = (const float*)d_in[0];
    const float* wq   = (const float*)d_in[1];
    const float* wk   = (const float*)d_in[2];
    const float* wv   = (const float*)d_in[3];
    const float* wo   = (const float*)d_in[4];
    const float* fcos = (const float*)d_in[5];
    const float* fsin = (const float*)d_in[6];
    float* outp = (float*)d_out;

    float *gq, *gk, *gv, *ga;
    cudaGetSymbolAddress((void**)&gq, g_q);
    cudaGetSymbolAddress((void**)&gk, g_k);
    cudaGetSymbolAddress((void**)&gv, g_v);
    cudaGetSymbolAddress((void**)&ga, g_attn);

    __nv_bfloat16 *xh, *xl, *ah, *al;
    __nv_bfloat16 *wqh, *wql, *wkh, *wkl, *wvh, *wvl, *woh, *wol;
    cudaGetSymbolAddress((void**)&xh, s_xh);   cudaGetSymbolAddress((void**)&xl, s_xl);
    cudaGetSymbolAddress((void**)&ah, s_ah);   cudaGetSymbolAddress((void**)&al, s_al);
    cudaGetSymbolAddress((void**)&wqh, s_wqh); cudaGetSymbolAddress((void**)&wql, s_wql);
    cudaGetSymbolAddress((void**)&wkh, s_wkh); cudaGetSymbolAddress((void**)&wkl, s_wkl);
    cudaGetSymbolAddress((void**)&wvh, s_wvh); cudaGetSymbolAddress((void**)&wvl, s_wvl);
    cudaGetSymbolAddress((void**)&woh, s_woh); cudaGetSymbolAddress((void**)&wol, s_wol);

    cudaFuncSetAttribute(flash_kernel,
                         cudaFuncAttributeMaxDynamicSharedMemorySize, FA_SMEM_BYTES);
    cudaFuncSetAttribute(gemm_bf16x3,
                         cudaFuncAttributeMaxDynamicSharedMemorySize, GEMM_SMEM);

    // ---- operand conversions ----
    {
        int n = NROWS * DMODEL;
        convert_split2<<<(n + 255) / 256, 256>>>(x, xh, xl, n);
    }
    transpose_split2<<<dim3(DMODEL / 32, DMODEL / 32), dim3(32, 8)>>>(wq, wqh, wql, DMODEL, DMODEL);
    transpose_split2<<<dim3(KVD / 32,    DMODEL / 32), dim3(32, 8)>>>(wk, wkh, wkl, DMODEL, KVD);
    transpose_split2<<<dim3(KVD / 32,    DMODEL / 32), dim3(32, 8)>>>(wv, wvh, wvl, DMODEL, KVD);
    transpose_split2<<<dim3(DMODEL / 32, DMODEL / 32), dim3(32, 8)>>>(wo, woh, wol, DMODEL, DMODEL);

    // ---- QKV projections (bf16 split mma) ----
    gemm_bf16x3<<<dim3(DMODEL / 128, NROWS / 128), 128, GEMM_SMEM>>>(
        xh, xl, wqh, wql, gq, DMODEL, DMODEL);
    gemm_bf16x3<<<dim3(KVD / 128, NROWS / 128), 128, GEMM_SMEM>>>(
        xh, xl, wkh, wkl, gk, DMODEL, KVD);
    gemm_bf16x3<<<dim3(KVD / 128, NROWS / 128), 128, GEMM_SMEM>>>(
        xh, xl, wvh, wvl, gv, DMODEL, KVD);

    // ---- RoPE ----
    {
        int totq = NROWS * NHEADS * 64;
        int totk = NROWS * NKVH * 64;
        rope_kernel<NHEADS><<<(totq + 255) / 256, 256>>>(gq, fcos, fsin, totq);
        rope_kernel<NKVH><<<(totk + 255) / 256, 256>>>(gk, fcos, fsin, totk);
    }

    // ---- Flash attention ----
    flash_kernel<<<dim3(SEQ / FA_BM, NHEADS, BATCH), 256, FA_SMEM_BYTES>>>(gq, gk, gv, ga);

    // ---- O projection ----
    {
        int n = NROWS * DMODEL;
        convert_split2<<<(n + 255) / 256, 256>>>(ga, ah, al, n);
    }
    gemm_bf16x3<<<dim3(DMODEL / 128, NROWS / 128), 128, GEMM_SMEM>>>(
        ah, al, woh, wol, outp, DMODEL, DMODEL);
}